// round 2
// baseline (speedup 1.0000x reference)
#include <cuda_runtime.h>
#include <math.h>

typedef unsigned long long ull;

// ---------------------------------------------------------------------------
// Packed f32x2 helpers (sm_103a FFMA2 path)
// ---------------------------------------------------------------------------
__device__ __forceinline__ ull pk2(float lo, float hi) {
    ull r; asm("mov.b64 %0, {%1, %2};" : "=l"(r) : "f"(lo), "f"(hi)); return r;
}
__device__ __forceinline__ void upk2(ull v, float& lo, float& hi) {
    asm("mov.b64 {%0, %1}, %2;" : "=f"(lo), "=f"(hi) : "l"(v));
}
__device__ __forceinline__ void fma2(ull& d, ull a, ull b) {
    asm("fma.rn.f32x2 %0, %1, %2, %0;" : "+l"(d) : "l"(a), "l"(b));
}

// ---------------------------------------------------------------------------
// Intermediate activation buffers (device globals — no allocation allowed).
// Layouts all [B, C, T, D, H, W] contiguous.
// ---------------------------------------------------------------------------
__device__ float g_a1[38880000];   // 256*3*15^4
__device__ float g_a2[15925248];   // 256*3*12^4
__device__ float g_a3[6718464];    // 256*4*9^4
__device__ float g_a4[1658880];    // 256*5*6^4

// ---------------------------------------------------------------------------
// Inner row engine: given a row pointer in SMEM (RL consecutive floats) and a
// weight pointer wq (per (ci,kt,kd,kh); co stride = COS, kw stride = 1),
// accumulate COUT x RP packed output pairs with fma.rn.f32x2.
// ---------------------------------------------------------------------------
template<int CO, int K, int RP, int COS>
__device__ __forceinline__ void row_fma2(const float* __restrict__ rsrc,
                                         const float* __restrict__ wq,
                                         ull (&acc)[CO][RP])
{
    constexpr int RL = 2 * RP + K - 1;
    float row[RL];
#pragma unroll
    for (int x = 0; x < RL; x++) row[x] = rsrc[x];

    constexpr int NE = RP + 1;                 // even-offset pairs
    constexpr int NO = RP + (K >= 4 ? 1 : 0);  // odd-offset pairs
    ull rowE[NE], rowO[NO];
#pragma unroll
    for (int j = 0; j < NE; j++) rowE[j] = pk2(row[2 * j], row[2 * j + 1]);
#pragma unroll
    for (int j = 0; j < NO; j++) rowO[j] = pk2(row[2 * j + 1], row[2 * j + 2]);

#pragma unroll
    for (int kw = 0; kw < K; kw++) {
#pragma unroll
        for (int co = 0; co < CO; co++) {
            const float w = wq[co * COS + kw];
            const ull w2 = pk2(w, w);
#pragma unroll
            for (int j = 0; j < RP; j++) {
                const ull a = (kw & 1) ? rowO[(kw >> 1) + j] : rowE[(kw >> 1) + j];
                fma2(acc[co][j], a, w2);
            }
        }
    }
}

// ---------------------------------------------------------------------------
// Kernel A: rolling t-slice conv (+bias+ReLU). Block = (b, t-chunk).
// Thread = (t_local, d, h), computes full W row for all COUT.
// Slices double-buffered in dynamic SMEM; weights staged in static SMEM.
// ---------------------------------------------------------------------------
template<int CIN, int COUT, int K, int S, int TLOC, int NTHR>
__global__ void __launch_bounds__(NTHR)
convA(const float* __restrict__ in, float* __restrict__ out,
      const float* __restrict__ w, const float* __restrict__ bias)
{
    constexpr int O = S - K + 1, TCH = O / TLOC, NST = TLOC + K - 1;
    constexpr int S2 = S * S, S3 = S2 * S, S4 = S3 * S;
    constexpr int O2 = O * O, O3 = O2 * O;
    constexpr int K4 = K * K * K * K, NW = COUT * CIN * K4, NACT = TLOC * O2;
    constexpr int RP = (O + 1) / 2;
    constexpr int SLP = S3 + 2;   // +pad for odd-O row overrun

    extern __shared__ float dsm[];        // 2 * SLP
    __shared__ float s_w[NW];

    const int bt = blockIdx.x, tch = bt % TCH, b = bt / TCH;
    const int t0 = tch * TLOC, tid = threadIdx.x;

    for (int i = tid; i < NW; i += NTHR) s_w[i] = w[i];

    const int tl = tid / O2, rem = tid - tl * O2, dd = rem / O, hh = rem - dd * O;
    const bool act = tid < NACT;

    ull acc[COUT][RP];
#pragma unroll
    for (int c = 0; c < COUT; c++)
#pragma unroll
        for (int j = 0; j < RP; j++) acc[c][j] = 0ull;

    constexpr int NSL = CIN * NST;
    {   // stage slice 0 into buffer 0
        const float* src = in + (size_t)b * CIN * S4 + (size_t)t0 * S3;
        for (int i = tid; i < S3; i += NTHR) dsm[i] = src[i];
    }
#pragma unroll 1
    for (int idx = 0; idx < NSL; idx++) {
        __syncthreads();
        if (idx + 1 < NSL) {    // prefetch next slice into the other buffer
            const int ci2 = (idx + 1) / NST, s2 = (idx + 1) - ci2 * NST;
            const float* src = in + ((size_t)b * CIN + ci2) * S4 + (size_t)(t0 + s2) * S3;
            float* dst = dsm + ((idx + 1) & 1) * SLP;
            for (int i = tid; i < S3; i += NTHR) dst[i] = src[i];
        }
        const int ci = idx / NST, s = idx - ci * NST;
        const int kt = s - tl;
        if (act && kt >= 0 && kt < K) {
            const float* buf = dsm + (idx & 1) * SLP;
#pragma unroll 1
            for (int kd = 0; kd < K; kd++) {
#pragma unroll 1
                for (int kh = 0; kh < K; kh++) {
                    const float* rp_ = buf + (dd + kd) * S2 + (hh + kh) * S;
                    const float* wq  = s_w + (((ci * K + kt) * K + kd) * K + kh) * K;
                    row_fma2<COUT, K, RP, CIN * K4>(rp_, wq, acc);
                }
            }
        }
    }

    if (act) {
        const int t = t0 + tl;
#pragma unroll
        for (int co = 0; co < COUT; co++) {
            const float bv = bias[co];
            float* op = out + ((size_t)b * COUT + co) * ((size_t)O * O3)
                            + (size_t)t * O3 + (dd * O + hh) * O;
#pragma unroll
            for (int j = 0; j < RP; j++) {
                float v0, v1; upk2(acc[co][j], v0, v1);
                op[2 * j] = fmaxf(v0 + bv, 0.0f);
                if (2 * j + 1 < O) op[2 * j + 1] = fmaxf(v1 + bv, 0.0f);
            }
        }
    }
}

// ---------------------------------------------------------------------------
// Kernel B: whole-volume conv for small layers. Block = b, thread = (t,d,h)
// covering ALL outputs. Stages the full 4D volume of one input channel at a
// time (double-buffered). Optional fused FC head (FC1+ReLU+FC2+sigmoid).
// ---------------------------------------------------------------------------
template<int CIN, int COUT, int K, int S, int NTHR, bool FUSE_FC>
__global__ void __launch_bounds__(NTHR)
convB(const float* __restrict__ in, float* __restrict__ out,
      const float* __restrict__ w, const float* __restrict__ bias,
      const float* __restrict__ fc1w, const float* __restrict__ fc1b,
      const float* __restrict__ fc2w, const float* __restrict__ fc2b)
{
    constexpr int O = S - K + 1;
    constexpr int S2 = S * S, S3 = S2 * S, S4 = S3 * S;
    constexpr int O2 = O * O, O3 = O2 * O, O4 = O * O3;
    constexpr int K4 = K * K * K * K, NW = COUT * CIN * K4;
    constexpr int NACT = O * O2;
    constexpr int RP = (O + 1) / 2;
    constexpr int VP = S4 + 2;

    extern __shared__ float dsm[];        // 2 * VP
    __shared__ float s_w[NW];
    __shared__ float s_h[FUSE_FC ? COUT * O4 : 1];
    __shared__ float s_so[FUSE_FC ? 33 : 1];

    const int b = blockIdx.x, tid = threadIdx.x;
    for (int i = tid; i < NW; i += NTHR) s_w[i] = w[i];

    const int tl = tid / O2, rem = tid - tl * O2, dd = rem / O, hh = rem - dd * O;
    const bool act = tid < NACT;

    ull acc[COUT][RP];
#pragma unroll
    for (int c = 0; c < COUT; c++)
#pragma unroll
        for (int j = 0; j < RP; j++) acc[c][j] = 0ull;

    {   // stage channel-0 volume
        const float* src = in + (size_t)b * CIN * S4;
        for (int i = tid; i < S4; i += NTHR) dsm[i] = src[i];
    }
#pragma unroll 1
    for (int ci = 0; ci < CIN; ci++) {
        __syncthreads();
        if (ci + 1 < CIN) {
            const float* src = in + ((size_t)b * CIN + ci + 1) * S4;
            float* dst = dsm + ((ci + 1) & 1) * VP;
            for (int i = tid; i < S4; i += NTHR) dst[i] = src[i];
        }
        if (act) {
            const float* buf = dsm + (ci & 1) * VP;
#pragma unroll 1
            for (int kt = 0; kt < K; kt++) {
                const float* sl = buf + (tl + kt) * S3;
#pragma unroll 1
                for (int kd = 0; kd < K; kd++) {
#pragma unroll 1
                    for (int kh = 0; kh < K; kh++) {
                        const float* rp_ = sl + (dd + kd) * S2 + (hh + kh) * S;
                        const float* wq  = s_w + (((ci * K + kt) * K + kd) * K + kh) * K;
                        row_fma2<COUT, K, RP, CIN * K4>(rp_, wq, acc);
                    }
                }
            }
        }
    }

    if (!FUSE_FC) {
        if (act) {
#pragma unroll
            for (int co = 0; co < COUT; co++) {
                const float bv = bias[co];
                float* op = out + ((size_t)b * COUT + co) * (size_t)O4
                                + (size_t)tl * O3 + (dd * O + hh) * O;
#pragma unroll
                for (int j = 0; j < RP; j++) {
                    float v0, v1; upk2(acc[co][j], v0, v1);
                    op[2 * j] = fmaxf(v0 + bv, 0.0f);
                    if (2 * j + 1 < O) op[2 * j + 1] = fmaxf(v1 + bv, 0.0f);
                }
            }
        }
    } else {
        // conv output -> SMEM (flatten order [co][t][d][h][w]) with bias+ReLU
        if (act) {
#pragma unroll
            for (int co = 0; co < COUT; co++) {
                const float bv = bias[co];
                float* op = s_h + co * O4 + tl * O3 + (dd * O + hh) * O;
#pragma unroll
                for (int j = 0; j < RP; j++) {
                    float v0, v1; upk2(acc[co][j], v0, v1);
                    op[2 * j] = fmaxf(v0 + bv, 0.0f);
                    if (2 * j + 1 < O) op[2 * j + 1] = fmaxf(v1 + bv, 0.0f);
                }
            }
        }
        __syncthreads();
        constexpr int NF = COUT * O4;   // 1280
        if (tid < 33) {
            const float* wr = fc1w + tid * NF;
            float a0 = 0.f, a1 = 0.f, a2 = 0.f, a3 = 0.f;
#pragma unroll 4
            for (int k = 0; k < NF; k += 4) {
                a0 = fmaf(s_h[k + 0], __ldg(wr + k + 0), a0);
                a1 = fmaf(s_h[k + 1], __ldg(wr + k + 1), a1);
                a2 = fmaf(s_h[k + 2], __ldg(wr + k + 2), a2);
                a3 = fmaf(s_h[k + 3], __ldg(wr + k + 3), a3);
            }
            s_so[tid] = fmaxf((a0 + a1) + (a2 + a3) + fc1b[tid], 0.0f);
        }
        __syncthreads();
        if (tid == 0) {
            float z = fc2b[0];
#pragma unroll
            for (int j = 0; j < 33; j++) z = fmaf(s_so[j], __ldg(fc2w + j), z);
            out[b] = 1.0f / (1.0f + expf(-z));
        }
    }
}

// ---------------------------------------------------------------------------
// Inputs (metadata order):
// 0:x 1:w1 2:b1 3:w2 4:b2 5:w3 6:b3 7:w4 8:b4 9:w5 10:b5
// 11:fc1_w 12:fc1_b 13:fc2_w 14:fc2_b    -> out: [B,1] float32
// ---------------------------------------------------------------------------
extern "C" void kernel_launch(void* const* d_in, const int* in_sizes, int n_in,
                              void* d_out, int out_size)
{
    const float* x   = (const float*)d_in[0];
    const float* w1  = (const float*)d_in[1];
    const float* b1  = (const float*)d_in[2];
    const float* w2  = (const float*)d_in[3];
    const float* b2  = (const float*)d_in[4];
    const float* w3  = (const float*)d_in[5];
    const float* b3  = (const float*)d_in[6];
    const float* w4  = (const float*)d_in[7];
    const float* b4  = (const float*)d_in[8];
    const float* w5  = (const float*)d_in[9];
    const float* b5  = (const float*)d_in[10];
    const float* f1w = (const float*)d_in[11];
    const float* f1b = (const float*)d_in[12];
    const float* f2w = (const float*)d_in[13];
    const float* f2b = (const float*)d_in[14];

    const int B = in_sizes[0] / (18 * 18 * 18 * 18);

    float *a1, *a2, *a3, *a4;
    cudaGetSymbolAddress((void**)&a1, g_a1);
    cudaGetSymbolAddress((void**)&a2, g_a2);
    cudaGetSymbolAddress((void**)&a3, g_a3);
    cudaGetSymbolAddress((void**)&a4, g_a4);

    constexpr int SM1 = 2 * (18 * 18 * 18 + 2) * 4;
    constexpr int SM2 = 2 * (15 * 15 * 15 + 2) * 4;
    constexpr int SM3 = 2 * (12 * 12 * 12 + 2) * 4;
    constexpr int SM4 = 2 * (9 * 9 * 9 * 9 + 2) * 4;
    constexpr int SM5 = 2 * (6 * 6 * 6 * 6 + 2) * 4;

    cudaFuncSetAttribute(convA<1, 3, 4, 18, 1, 256>,
                         cudaFuncAttributeMaxDynamicSharedMemorySize, SM1);
    cudaFuncSetAttribute(convA<3, 3, 4, 15, 1, 160>,
                         cudaFuncAttributeMaxDynamicSharedMemorySize, SM2);
    cudaFuncSetAttribute(convA<3, 4, 4, 12, 3, 256>,
                         cudaFuncAttributeMaxDynamicSharedMemorySize, SM3);
    cudaFuncSetAttribute(convB<4, 5, 4, 9, 224, false>,
                         cudaFuncAttributeMaxDynamicSharedMemorySize, SM4);
    cudaFuncSetAttribute(convB<5, 5, 3, 6, 64, true>,
                         cudaFuncAttributeMaxDynamicSharedMemorySize, SM5);

    // L1: 18^4 -> 15^4, 1->3, k=4
    convA<1, 3, 4, 18, 1, 256><<<B * 15, 256, SM1>>>(x,  a1, w1, b1);
    // L2: 15^4 -> 12^4, 3->3, k=4
    convA<3, 3, 4, 15, 1, 160><<<B * 12, 160, SM2>>>(a1, a2, w2, b2);
    // L3: 12^4 -> 9^4, 3->4, k=4  (TLOC=3: 243 active / 256)
    convA<3, 4, 4, 12, 3, 256><<<B * 3, 256, SM3>>>(a2, a3, w3, b3);
    // L4: 9^4 -> 6^4, 4->5, k=4   (block=b, 216 active / 224)
    convB<4, 5, 4, 9, 224, false><<<B, 224, SM4>>>(a3, a4, w4, b4,
                                                   nullptr, nullptr, nullptr, nullptr);
    // L5: 6^4 -> 4^4, 5->5, k=3  + fused FC1/ReLU/FC2/sigmoid -> d_out [B,1]
    convB<5, 5, 3, 6, 64, true><<<B, 64, SM5>>>(a4, (float*)d_out, w5, b5,
                                                f1w, f1b, f2w, f2b);
}